// round 8
// baseline (speedup 1.0000x reference)
#include <cuda_runtime.h>
#include <cstdint>

// Dendrite_755914244697 — persistent double-buffered cp.async.bulk pipeline.
// 8 CTAs/SM x 128 threads: 8 small independent copy streams per SM (12.8KB
// stages) to smooth the HBM stream. Lane pair (2i,2i+1) shares one output
// with a PARITY k-split (lane h takes k=2i+h); hot loop has no runtime selects
// (pad element load is clamped in-bounds at compile time and its value
// neutralized to 1.0).
// out[o] = log( prod_{k<25} (1.1 + atan(10*(p[k]*w[o*25+k] - q[o*25+k]))/pi) )

#define IMG   128
#define OUTD  124
#define SIDE  5
#define SEG   25
#define TPB   128
#define TILE  64
#define NS    2
#define KH    13                               // k-elements per lane (padded)
#define TILE_BYTES  (TILE * SEG * 4)           // 6400 B per array per tile
#define STAGE_BYTES (2 * TILE_BYTES)           // w + q = 12800 B
#define SMEM_BYTES  (256 + NS * STAGE_BYTES)   // 25856 B per CTA

__device__ __forceinline__ uint32_t smem_u32(const void* p)
{
    uint32_t a;
    asm("{ .reg .u64 t; cvta.to.shared.u64 t, %1; cvt.u32.u64 %0, t; }"
        : "=r"(a) : "l"(p));
    return a;
}

__device__ __forceinline__ void mbar_init(uint32_t mb, uint32_t count)
{
    asm volatile("mbarrier.init.shared.b64 [%0], %1;" :: "r"(mb), "r"(count) : "memory");
}

__device__ __forceinline__ void mbar_expect_tx(uint32_t mb, uint32_t bytes)
{
    asm volatile("mbarrier.arrive.expect_tx.shared.b64 _, [%0], %1;"
                 :: "r"(mb), "r"(bytes) : "memory");
}

__device__ __forceinline__ void bulk_g2s(uint32_t dst, const void* src,
                                         uint32_t bytes, uint32_t mb)
{
    asm volatile("cp.async.bulk.shared::cta.global.mbarrier::complete_tx::bytes "
                 "[%0], [%1], %2, [%3];"
                 :: "r"(dst), "l"(src), "r"(bytes), "r"(mb) : "memory");
}

__device__ __forceinline__ void mbar_wait(uint32_t mb, uint32_t phase)
{
    uint32_t done;
    asm volatile(
        "{ .reg .pred p;\n"
        "  mbarrier.try_wait.parity.acquire.cta.shared::cta.b64 p, [%1], %2;\n"
        "  selp.b32 %0, 1, 0, p; }"
        : "=r"(done) : "r"(mb), "r"(phase) : "memory");
    while (!done) {
        asm volatile(
            "{ .reg .pred p;\n"
            "  mbarrier.try_wait.parity.acquire.cta.shared::cta.b64 p, [%1], %2, 0x989680;\n"
            "  selp.b32 %0, 1, 0, p; }"
            : "=r"(done) : "r"(mb), "r"(phase) : "memory");
    }
}

// v(u) = 1.1 + atan(u)/pi. 5-coeff minimax (max err ~1e-5 rad).
__device__ __forceinline__ float v_of(float u)
{
    float inv;
    asm("rcp.approx.f32 %0, %1;" : "=f"(inv) : "f"(u));   // signed reciprocal
    bool  big = fabsf(u) > 1.0f;
    float z   = big ? inv : u;
    float s   = z * z;
    float p   =              0.0208351f;
    p = __fmaf_rn(p, s, -0.0851330f);
    p = __fmaf_rn(p, s,  0.1801410f);
    p = __fmaf_rn(p, s, -0.3302995f);
    p = __fmaf_rn(p, s,  0.9998660f);
    float r = p * z;                                       // atan(z), signed
    float c = __uint_as_float(0x3fc90fdbu |
                              (__float_as_uint(u) & 0x80000000u));
    float a = big ? (c - r) : r;
    return __fmaf_rn(a, 0.31830988618379067f, 1.1f);
}

__global__ void __launch_bounds__(TPB, 8)
dendrite_kernel(const float* __restrict__ x,
                const float* __restrict__ w,
                const float* __restrict__ q,
                float*       __restrict__ out,
                int n_out)
{
    extern __shared__ char smem[];
    const uint32_t sb  = smem_u32(smem);
    const uint32_t mb0 = sb;                       // NS mbarriers at [0, 16)
    float* buf = reinterpret_cast<float*>(smem + 256);

    const int tid = threadIdx.x;

    if (tid == 0) {
#pragma unroll
        for (int i = 0; i < NS; ++i) mbar_init(mb0 + 8 * i, 1);
        asm volatile("fence.proxy.async.shared::cta;" ::: "memory");
    }
    __syncthreads();

    const int ntiles = (n_out + TILE - 1) / TILE;
    int t = blockIdx.x;
    if (t >= ntiles) return;
    const int G = gridDim.x;

    auto issue = [&](int st, int tile) {
        const int cnt     = min(TILE, n_out - tile * TILE);
        const uint32_t nb = (uint32_t)cnt * SEG * 4;     // multiple of 16 here
        const uint32_t mb = mb0 + st * 8;
        const uint32_t dw = sb + 256 + st * STAGE_BYTES;
        const size_t  off = (size_t)tile * TILE_BYTES;
        mbar_expect_tx(mb, 2 * nb);
        bulk_g2s(dw,              (const char*)w + off, nb, mb);
        bulk_g2s(dw + TILE_BYTES, (const char*)q + off, nb, mb);
    };

    if (tid == 0) issue(0, t);     // prefill stage 0

    const float LN2 = 0.69314718055994531f;

    const int lo = tid >> 1;       // local output index 0..63
    const int h  = tid & 1;        // parity half: lane handles k = 2i+h

    for (int j = 0; t < ntiles; ++j, t += G) {
        const int s = j & 1;

        // Refill the other stage (freed by last iteration's __syncthreads).
        if (tid == 0) {
            const int tn = t + G;
            if (tn < ntiles) issue(s ^ 1, tn);
        }

        // ---- x-patch loads: independent of staged data, hidden under copy ----
        const int o      = t * TILE + lo;
        const bool active = (o < n_out);
        const int oc = active ? o : (n_out - 1);
        const int sp = oc / 25;
        const int c  = sp / (OUTD * OUTD);
        const int rr = sp - c * (OUTD * OUTD);
        const int oy = rr / OUTD;
        const int ox = rr - oy * OUTD;
        const float* __restrict__ xp = x + (c * IMG + oy) * IMG + ox;

        float pv[KH];
#pragma unroll
        for (int i = 0; i < KH; ++i) {
            const int ke  = 2 * i;                              // h=0 k
            const int ko  = (2 * i + 1 < SEG) ? 2 * i + 1 : 0;  // h=1 k (pad->0)
            const int oe  = (ke / 5) * IMG + (ke % 5);
            const int oo  = (ko / 5) * IMG + (ko % 5);
            pv[i] = __ldg(xp + (h ? oo : oe));                  // sels hidden here
        }

        mbar_wait(mb0 + s * 8, (uint32_t)(j >> 1) & 1u);

        {
            // Hot loop: element i lives at base + 2*i — no runtime selects.
            // Pad element (h=1, i=KH-1, logical k=25) would read 1 float past
            // the stage: clamp its smem offset to 0 (compile-time, loop is
            // unrolled) and neutralize its value to 1.0.
            const float* wr = buf + s * (STAGE_BYTES / 4) + lo * SEG + h;
            const float* qr = wr + TILE_BYTES / 4;

            float pr0 = 1.0f, pr1 = 1.0f, pr2 = 1.0f;
#pragma unroll
            for (int i = 0; i < KH; ++i) {
                const int idx = (2 * i + 1 < SEG) ? 2 * i : (h ? 0 : 2 * i);
                float tt = __fmaf_rn(pv[i], wr[idx], -qr[idx]);
                float v  = v_of(10.0f * tt);
                if (h && i == KH - 1) v = 1.0f;          // neutralize pad (k=25)
                if      (i % 3 == 0) pr0 *= v;
                else if (i % 3 == 1) pr1 *= v;
                else                 pr2 *= v;
            }
            float myp  = (pr0 * pr1) * pr2;
            float othp = __shfl_xor_sync(0xffffffffu, myp, 1);
            if (active && h == 0)
                out[o] = __log2f(myp * othp) * LN2;
        }
        __syncthreads();   // stage s fully consumed -> refillable next iteration
    }
}

extern "C" void kernel_launch(void* const* d_in, const int* in_sizes, int n_in,
                              void* d_out, int out_size)
{
    const float* x = (const float*)d_in[0];
    const float* w = (const float*)d_in[1];
    const float* q = (const float*)d_in[2];
    float* out = (float*)d_out;

    cudaFuncSetAttribute(dendrite_kernel,
                         cudaFuncAttributeMaxDynamicSharedMemorySize, SMEM_BYTES);

    int sm = 148;
    cudaDeviceGetAttribute(&sm, cudaDevAttrMultiProcessorCount, 0);

    const int n_out  = out_size;                     // 1,153,200
    const int ntiles = (n_out + TILE - 1) / TILE;    // 18019
    int grid = sm * 8;
    if (grid > ntiles) grid = ntiles;

    dendrite_kernel<<<grid, TPB, SMEM_BYTES>>>(x, w, q, out, n_out);
}